// round 2
// baseline (speedup 1.0000x reference)
#include <cuda_runtime.h>
#include <cuda_bf16.h>
#include <cstdint>

// PCEN with 10 smoother coefficients.
//   m[s,b,f,t] = (1-s)*m[s,b,f,t-1] + s*x[b,f,t],  m[...,0] = x[b,f,0]
//   smooth = exp(-alpha*(log(EPS) + log1p(m/EPS))) = (EPS + m)^(-alpha)
//   out[b,s,f,t] = (x*smooth + delta)^r - delta^r
//
// One warp per (b,f) row. Warp-parallel scan of the constant-coefficient
// linear recurrence (Kogge-Stone with precomputed a^d), 10 s-values kept in
// register arrays, x loaded once per element, fully coalesced loads/stores.

#define PCEN_EPS 1e-5f
#define NS 10
#define TT 2048
#define NCHUNK (TT / 32)

__device__ __forceinline__ float fast_ex2(float v) {
    float r;
    asm("ex2.approx.ftz.f32 %0, %1;" : "=f"(r) : "f"(v));
    return r;
}
__device__ __forceinline__ float fast_lg2(float v) {
    float r;
    asm("lg2.approx.ftz.f32 %0, %1;" : "=f"(r) : "f"(v));
    return r;
}

__global__ __launch_bounds__(128) void pcen_kernel(
    const float* __restrict__ x,
    const float* __restrict__ s_log,
    const float* __restrict__ alpha_log,
    const float* __restrict__ delta_log,
    const float* __restrict__ r_log,
    float* __restrict__ out,
    int F, int BF)
{
    const int warp = (blockIdx.x * blockDim.x + threadIdx.x) >> 5;
    const int lane = threadIdx.x & 31;
    if (warp >= BF) return;

    const int b = warp / F;
    const int f = warp % F;

    const float alpha = __expf(alpha_log[f]);
    const float delta = __expf(delta_log[f]);
    const float r     = __expf(r_log[f]);
    const float delta_r = fast_ex2(r * fast_lg2(delta));

    const float* __restrict__ xp = x + (size_t)warp * TT;
    float* __restrict__ op = out + ((size_t)b * NS * F + f) * (size_t)TT;
    const size_t s_stride = (size_t)F * TT;

    // Per-s scan constants (register arrays; fully unrolled indexing)
    float sv[NS], a1[NS], a2[NS], a4[NS], a8[NS], a16[NS], apl[NS], carry[NS];

    const float x0 = xp[0];

    #pragma unroll
    for (int i = 0; i < NS; i++) {
        const float s = __expf(s_log[i]);
        sv[i] = s;
        const float a = 1.0f - s;
        a1[i]  = a;
        a2[i]  = a * a;
        a4[i]  = a2[i] * a2[i];
        a8[i]  = a4[i] * a4[i];
        a16[i] = a8[i] * a8[i];
        // a^(lane+1), exact product over set bits (e in [1,32])
        const int e = lane + 1;
        float ap = 1.0f;
        if (e & 1)  ap *= a;
        if (e & 2)  ap *= a2[i];
        if (e & 4)  ap *= a4[i];
        if (e & 8)  ap *= a8[i];
        if (e & 16) ap *= a16[i];
        if (e & 32) ap *= a16[i] * a16[i];
        apl[i] = ap;
        // m_{-1} := x0 makes m_0 = (1-s)*x0 + s*x0 = x0 (matches reference init)
        carry[i] = x0;
    }

    for (int c = 0; c < NCHUNK; c++) {
        const int t = c * 32 + lane;
        const float xv = xp[t];

        #pragma unroll
        for (int i = 0; i < NS; i++) {
            // inclusive scan of y_t = a*y_{t-1} + s*x_t within the 32-chunk
            float y = sv[i] * xv;
            float v;
            v = __shfl_up_sync(0xFFFFFFFFu, y, 1);  if (lane >= 1)  y = fmaf(a1[i],  v, y);
            v = __shfl_up_sync(0xFFFFFFFFu, y, 2);  if (lane >= 2)  y = fmaf(a2[i],  v, y);
            v = __shfl_up_sync(0xFFFFFFFFu, y, 4);  if (lane >= 4)  y = fmaf(a4[i],  v, y);
            v = __shfl_up_sync(0xFFFFFFFFu, y, 8);  if (lane >= 8)  y = fmaf(a8[i],  v, y);
            v = __shfl_up_sync(0xFFFFFFFFu, y, 16); if (lane >= 16) y = fmaf(a16[i], v, y);
            // fold in carry from previous chunk: m = y + a^(lane+1)*carry
            y = fmaf(apl[i], carry[i], y);
            carry[i] = __shfl_sync(0xFFFFFFFFu, y, 31);

            // smooth = (EPS + m)^(-alpha); pcen = (x*smooth + delta)^r - delta^r
            const float lg     = fast_lg2(PCEN_EPS + y);
            const float smooth = fast_ex2(-alpha * lg);
            const float base   = fmaf(xv, smooth, delta);
            const float p      = fast_ex2(r * fast_lg2(base));
            op[(size_t)i * s_stride + t] = p - delta_r;
        }
    }
}

extern "C" void kernel_launch(void* const* d_in, const int* in_sizes, int n_in,
                              void* d_out, int out_size)
{
    const float* x         = (const float*)d_in[0];
    const float* s_log     = (const float*)d_in[1];
    const float* alpha_log = (const float*)d_in[2];
    const float* delta_log = (const float*)d_in[3];
    const float* r_log     = (const float*)d_in[4];
    float* out = (float*)d_out;

    const int F  = in_sizes[2];          // alpha_log has F elements
    const int BF = in_sizes[0] / TT;     // number of (b,f) rows

    const int threads = 128;             // 4 warps per block
    const int warps_per_block = threads / 32;
    const int blocks = (BF + warps_per_block - 1) / warps_per_block;

    pcen_kernel<<<blocks, threads>>>(x, s_log, alpha_log, delta_log, r_log,
                                     out, F, BF);
}

// round 3
// speedup vs baseline: 1.1849x; 1.1849x over previous
#include <cuda_runtime.h>
#include <cuda_bf16.h>
#include <cstdint>

// PCEN with 10 smoother coefficients.
//   m[s,b,f,t] = (1-s)*m[s,b,f,t-1] + s*x[b,f,t],  m[...,0] = x[b,f,0]
//   smooth = (EPS + m)^(-alpha)
//   out[b,s,f,t] = (x*smooth + delta)^r - delta^r
//
// R3: split the 10 chains across warps (2 chains per warp) to raise occupancy
// from ~14 warps/SM (grid-limited) to ~69 warps/SM. Warp Kogge-Stone scan for
// the IIR, coalesced loads/stores. Warps of the same row are adjacent so x
// stays hot in L1/L2 across the 5 chain-pair warps.

#define PCEN_EPS 1e-5f
#define NS 10
#define CPW 2                 // chains per warp
#define NPAIR (NS / CPW)      // 5 warps per row
#define TT 2048
#define NCHUNK (TT / 32)

__device__ __forceinline__ float fast_ex2(float v) {
    float r;
    asm("ex2.approx.ftz.f32 %0, %1;" : "=f"(r) : "f"(v));
    return r;
}
__device__ __forceinline__ float fast_lg2(float v) {
    float r;
    asm("lg2.approx.ftz.f32 %0, %1;" : "=f"(r) : "f"(v));
    return r;
}

__global__ __launch_bounds__(128) void pcen_kernel(
    const float* __restrict__ x,
    const float* __restrict__ s_log,
    const float* __restrict__ alpha_log,
    const float* __restrict__ delta_log,
    const float* __restrict__ r_log,
    float* __restrict__ out,
    int F, int BF)
{
    const int gwarp = (blockIdx.x * blockDim.x + threadIdx.x) >> 5;
    const int lane  = threadIdx.x & 31;
    if (gwarp >= BF * NPAIR) return;

    const int row  = gwarp / NPAIR;   // adjacent warps share a row -> x L1/L2 hot
    const int pair = gwarp % NPAIR;
    const int i0   = pair * CPW;

    const int b = row / F;
    const int f = row % F;

    const float alpha = __expf(alpha_log[f]);
    const float delta = __expf(delta_log[f]);
    const float r     = __expf(r_log[f]);
    const float delta_r = fast_ex2(r * fast_lg2(delta));

    const float* __restrict__ xp = x + (size_t)row * TT;
    float* __restrict__ op = out + (((size_t)b * NS + i0) * F + f) * (size_t)TT;
    const size_t s_stride = (size_t)F * TT;

    // Per-chain scan constants
    float sv[CPW], a1[CPW], a2[CPW], a4[CPW], a8[CPW], a16[CPW], apl[CPW], carry[CPW];

    const float x0 = xp[0];

    #pragma unroll
    for (int c = 0; c < CPW; c++) {
        const float s = __expf(s_log[i0 + c]);
        sv[c] = s;
        const float a = 1.0f - s;
        a1[c]  = a;
        a2[c]  = a * a;
        a4[c]  = a2[c] * a2[c];
        a8[c]  = a4[c] * a4[c];
        a16[c] = a8[c] * a8[c];
        // a^(lane+1), exact product over set bits (e in [1,32])
        const int e = lane + 1;
        float ap = 1.0f;
        if (e & 1)  ap *= a;
        if (e & 2)  ap *= a2[c];
        if (e & 4)  ap *= a4[c];
        if (e & 8)  ap *= a8[c];
        if (e & 16) ap *= a16[c];
        if (e & 32) ap *= a16[c] * a16[c];
        apl[c] = ap;
        // m_{-1} := x0 makes m_0 = (1-s)*x0 + s*x0 = x0 (matches reference init)
        carry[c] = x0;
    }

    #pragma unroll 2
    for (int ch = 0; ch < NCHUNK; ch++) {
        const int t = ch * 32 + lane;
        const float xv = xp[t];

        #pragma unroll
        for (int c = 0; c < CPW; c++) {
            // inclusive scan of y_t = a*y_{t-1} + s*x_t within the 32-chunk
            float y = sv[c] * xv;
            float v;
            v = __shfl_up_sync(0xFFFFFFFFu, y, 1);  if (lane >= 1)  y = fmaf(a1[c],  v, y);
            v = __shfl_up_sync(0xFFFFFFFFu, y, 2);  if (lane >= 2)  y = fmaf(a2[c],  v, y);
            v = __shfl_up_sync(0xFFFFFFFFu, y, 4);  if (lane >= 4)  y = fmaf(a4[c],  v, y);
            v = __shfl_up_sync(0xFFFFFFFFu, y, 8);  if (lane >= 8)  y = fmaf(a8[c],  v, y);
            v = __shfl_up_sync(0xFFFFFFFFu, y, 16); if (lane >= 16) y = fmaf(a16[c], v, y);
            // fold in carry from previous chunk: m = y + a^(lane+1)*carry
            y = fmaf(apl[c], carry[c], y);
            carry[c] = __shfl_sync(0xFFFFFFFFu, y, 31);

            // smooth = (EPS + m)^(-alpha); pcen = (x*smooth + delta)^r - delta^r
            const float lg     = fast_lg2(PCEN_EPS + y);
            const float smooth = fast_ex2(-alpha * lg);
            const float base   = fmaf(xv, smooth, delta);
            const float p      = fast_ex2(r * fast_lg2(base));
            op[(size_t)c * s_stride + t] = p - delta_r;
        }
    }
}

extern "C" void kernel_launch(void* const* d_in, const int* in_sizes, int n_in,
                              void* d_out, int out_size)
{
    const float* x         = (const float*)d_in[0];
    const float* s_log     = (const float*)d_in[1];
    const float* alpha_log = (const float*)d_in[2];
    const float* delta_log = (const float*)d_in[3];
    const float* r_log     = (const float*)d_in[4];
    float* out = (float*)d_out;

    const int F  = in_sizes[2];          // alpha_log has F elements
    const int BF = in_sizes[0] / TT;     // number of (b,f) rows

    const int total_warps = BF * NPAIR;
    const int threads = 128;             // 4 warps per block
    const int warps_per_block = threads / 32;
    const int blocks = (total_warps + warps_per_block - 1) / warps_per_block;

    pcen_kernel<<<blocks, threads>>>(x, s_log, alpha_log, delta_log, r_log,
                                     out, F, BF);
}

// round 4
// speedup vs baseline: 1.5162x; 1.2797x over previous
#include <cuda_runtime.h>
#include <cuda_bf16.h>
#include <cstdint>

// PCEN, 10 smoother coefficients.
//   m[s,t] = (1-s)*m[s,t-1] + s*x[t],  m[s,0] = x[0]
//   out = (x*(EPS+m)^(-alpha) + delta)^r - delta^r
//
// R4: thread-serial (4 consecutive t per lane via float4) x warp-parallel scan.
// Per 128-t chunk per chain: 4-step local IIR, 5-hop Kogge-Stone on lane
// aggregates (ratio a^4), exclusive-prefix fold. 7 SHFLs per 128 t (was 24),
// float4 loads/stores. 2 chains per warp, 5 warps per (b,f) row.

#define PCEN_EPS 1e-5f
#define NS 10
#define CPW 2
#define NPAIR (NS / CPW)
#define TT 2048
#define RPT 4                    // timesteps per lane per chunk (float4)
#define CHUNK (32 * RPT)         // 128
#define NCHUNK (TT / CHUNK)      // 16

__device__ __forceinline__ float fast_ex2(float v) {
    float r; asm("ex2.approx.ftz.f32 %0, %1;" : "=f"(r) : "f"(v)); return r;
}
__device__ __forceinline__ float fast_lg2(float v) {
    float r; asm("lg2.approx.ftz.f32 %0, %1;" : "=f"(r) : "f"(v)); return r;
}

__global__ __launch_bounds__(128) void pcen_kernel(
    const float* __restrict__ x,
    const float* __restrict__ s_log,
    const float* __restrict__ alpha_log,
    const float* __restrict__ delta_log,
    const float* __restrict__ r_log,
    float* __restrict__ out,
    int F, int BF)
{
    const int gwarp = (blockIdx.x * blockDim.x + threadIdx.x) >> 5;
    const int lane  = threadIdx.x & 31;
    if (gwarp >= BF * NPAIR) return;

    const int row  = gwarp / NPAIR;
    const int pair = gwarp % NPAIR;
    const int i0   = pair * CPW;

    const int b = row / F;
    const int f = row % F;

    const float alpha = __expf(alpha_log[f]);
    const float delta = __expf(delta_log[f]);
    const float r     = __expf(r_log[f]);
    const float delta_r = fast_ex2(r * fast_lg2(delta));

    const float4* __restrict__ xp4 = (const float4*)(x + (size_t)row * TT);
    float* __restrict__ op = out + (((size_t)b * NS + i0) * F + f) * (size_t)TT;
    const size_t s_stride = (size_t)F * TT;

    // per-chain constants
    float sv[CPW], a1[CPW], a2[CPW], a3[CPW], a4[CPW];
    float a8[CPW], a16[CPW], a32[CPW], a64[CPW];
    float a4lane[CPW], a128[CPW], carry[CPW];

    const float x0 = ((const float*)xp4)[0];

    #pragma unroll
    for (int c = 0; c < CPW; c++) {
        const float s = __expf(s_log[i0 + c]);
        sv[c] = s;
        const float a = 1.0f - s;
        a1[c]  = a;
        a2[c]  = a * a;
        a3[c]  = a2[c] * a;
        a4[c]  = a2[c] * a2[c];
        a8[c]  = a4[c] * a4[c];
        a16[c] = a8[c] * a8[c];
        a32[c] = a16[c] * a16[c];
        a64[c] = a32[c] * a32[c];
        a128[c] = a64[c] * a64[c];
        // (a^4)^lane via set bits of lane
        float ap = 1.0f;
        if (lane & 1)  ap *= a4[c];
        if (lane & 2)  ap *= a8[c];
        if (lane & 4)  ap *= a16[c];
        if (lane & 8)  ap *= a32[c];
        if (lane & 16) ap *= a64[c];
        a4lane[c] = ap;
        // m_{-1} := x0 gives m_0 = (1-s)*x0 + s*x0 = x0 (reference init)
        carry[c] = x0;
    }

    for (int ch = 0; ch < NCHUNK; ch++) {
        const float4 xv = xp4[ch * 32 + lane];

        #pragma unroll
        for (int c = 0; c < CPW; c++) {
            const float s = sv[c];
            // local serial IIR with zero initial condition
            const float l0 = s * xv.x;
            const float l1 = fmaf(a1[c], l0, s * xv.y);
            const float l2 = fmaf(a1[c], l1, s * xv.z);
            const float l3 = fmaf(a1[c], l2, s * xv.w);

            // Kogge-Stone inclusive scan of lane aggregates (ratio a^4)
            float S = l3;
            float v;
            v = __shfl_up_sync(0xFFFFFFFFu, S, 1);  if (lane >= 1)  S = fmaf(a4[c],  v, S);
            v = __shfl_up_sync(0xFFFFFFFFu, S, 2);  if (lane >= 2)  S = fmaf(a8[c],  v, S);
            v = __shfl_up_sync(0xFFFFFFFFu, S, 4);  if (lane >= 4)  S = fmaf(a16[c], v, S);
            v = __shfl_up_sync(0xFFFFFFFFu, S, 8);  if (lane >= 8)  S = fmaf(a32[c], v, S);
            v = __shfl_up_sync(0xFFFFFFFFu, S, 16); if (lane >= 16) S = fmaf(a64[c], v, S);

            // M_prev: final m just before this lane's segment
            const float P = __shfl_up_sync(0xFFFFFFFFu, S, 1);
            const float Mprev = (lane == 0) ? carry[c]
                                            : fmaf(a4lane[c], carry[c], P);
            // chunk carry for next iteration: E_31 = S_31 + a^128 * carry
            const float S31 = __shfl_sync(0xFFFFFFFFu, S, 31);
            carry[c] = fmaf(a128[c], carry[c], S31);

            // fold prefix: m_j = l_j + a^{j+1} * Mprev
            const float m0 = fmaf(a1[c], Mprev, l0);
            const float m1 = fmaf(a2[c], Mprev, l1);
            const float m2 = fmaf(a3[c], Mprev, l2);
            const float m3 = fmaf(a4[c], Mprev, l3);

            // pcen elementwise
            float4 o;
            {
                const float sm = fast_ex2(-alpha * fast_lg2(PCEN_EPS + m0));
                o.x = fast_ex2(r * fast_lg2(fmaf(xv.x, sm, delta))) - delta_r;
            }
            {
                const float sm = fast_ex2(-alpha * fast_lg2(PCEN_EPS + m1));
                o.y = fast_ex2(r * fast_lg2(fmaf(xv.y, sm, delta))) - delta_r;
            }
            {
                const float sm = fast_ex2(-alpha * fast_lg2(PCEN_EPS + m2));
                o.z = fast_ex2(r * fast_lg2(fmaf(xv.z, sm, delta))) - delta_r;
            }
            {
                const float sm = fast_ex2(-alpha * fast_lg2(PCEN_EPS + m3));
                o.w = fast_ex2(r * fast_lg2(fmaf(xv.w, sm, delta))) - delta_r;
            }
            *(float4*)(op + (size_t)c * s_stride + (size_t)ch * CHUNK + lane * RPT) = o;
        }
    }
}

extern "C" void kernel_launch(void* const* d_in, const int* in_sizes, int n_in,
                              void* d_out, int out_size)
{
    const float* x         = (const float*)d_in[0];
    const float* s_log     = (const float*)d_in[1];
    const float* alpha_log = (const float*)d_in[2];
    const float* delta_log = (const float*)d_in[3];
    const float* r_log     = (const float*)d_in[4];
    float* out = (float*)d_out;

    const int F  = in_sizes[2];
    const int BF = in_sizes[0] / TT;

    const int total_warps = BF * NPAIR;
    const int threads = 128;
    const int warps_per_block = threads / 32;
    const int blocks = (total_warps + warps_per_block - 1) / warps_per_block;

    pcen_kernel<<<blocks, threads>>>(x, s_log, alpha_log, delta_log, r_log,
                                     out, F, BF);
}